// round 8
// baseline (speedup 1.0000x reference)
#include <cuda_runtime.h>

typedef unsigned long long ull;

#define T_STEPS 1024
#define BATCH   64
#define NCTA    128
#define NTHR    768

// Per-step input vector v (K=1024 rows x 64 batch), 8 chunks of 128 rows:
//   rows [0,256)    = x_t       (chunks 0-1, layer0 only)
//   rows [256,768)  = h0_{t-1}  (chunks 2-5, both layers)
//   rows [768,1024) = h1_{t-2}  (chunks 6-7, layer1 only)
// L0 GEMM: global k in [0,768).  L1 GEMM: local k1 = k-256 in [0,768).
//
// Thread mapping (24 warps): ks = warp id in [0,24) -> k = ks (mod 24), strided.
//   lane: pg = (lane>>2) in [0,8) -> pairs 4pg..4pg+3 (batches 8pg..8pg+7)
//         cg = lane&3:  L0 gate-group cg (cols 4cg..4cg+3 = units 0..3 of gate cg)
//                       L1 group cg (cols 2cg, 2cg+1 = units 0,1 of gate cg)
// Accums: a0[4 cols][4 pairs] + a1[2 cols][4 pairs] = 24 ull.
// 24 ks-partials reduced in 3 waves (8 slots) through smem aliased over vbuf.

__device__ float g_xT[T_STEPS * 256 * BATCH];   // x transposed to [t][k][b]
__device__ float g_h0[2][512 * BATCH];
__device__ float g_h1[2][256 * BATCH];
__device__ unsigned g_count = 0;
__device__ volatile unsigned g_phase = 0;

__device__ __forceinline__ ull ffma2(ull a, ull b, ull c) {
    ull d;
    asm("fma.rn.f32x2 %0, %1, %2, %3;" : "=l"(d) : "l"(a), "l"(b), "l"(c));
    return d;
}
__device__ __forceinline__ ull addf2(ull a, ull b) {
    ull d;
    asm("add.rn.f32x2 %0, %1, %2;" : "=l"(d) : "l"(a), "l"(b));
    return d;
}
__device__ __forceinline__ ull dup32(float w) {
    unsigned u = __float_as_uint(w);
    return ((ull)u << 32) | (ull)u;
}
__device__ __forceinline__ float sigmf(float x) {
    return 1.0f / (1.0f + __expf(-x));
}

__device__ __forceinline__ void cp16(float* smp, const float* gp) {
    unsigned a = (unsigned)__cvta_generic_to_shared(smp);
    asm volatile("cp.async.cg.shared.global [%0], [%1], 16;" :: "r"(a), "l"(gp));
}
#define CP_COMMIT asm volatile("cp.async.commit_group;" ::: "memory")
#define CP_WAIT1  asm volatile("cp.async.wait_group 1;" ::: "memory")
#define CP_WAIT0  asm volatile("cp.async.wait_group 0;" ::: "memory")

// Sense-reversing grid barrier. Safe: 219KB smem -> 1 CTA/SM, 128 CTAs <= 148 SMs,
// all co-resident in wave 1. Count self-resets -> consistent across graph replays.
__device__ __forceinline__ void grid_barrier() {
    __syncthreads();
    if (threadIdx.x == 0) {
        __threadfence();
        unsigned ph = g_phase;
        if (atomicAdd(&g_count, 1u) == (unsigned)(gridDim.x - 1)) {
            atomicExch(&g_count, 0u);
            __threadfence();
            g_phase = ph + 1u;
        } else {
            while (g_phase == ph) { __nanosleep(32); }
            __threadfence();
        }
    }
    __syncthreads();
}

// Stage one 128x64 chunk (32KB) into smem via cp.async (or zeros). Always commits
// one group so wait_group counting stays uniform across paths.
__device__ __forceinline__ void stage_chunk(float* dst, int c, int t, int tid) {
    const float* src;
    if (c < 2)       src = g_xT + (size_t)t * 16384 + c * 8192;
    else if (c < 6)  src = (t >= 1) ? (g_h0[(t - 1) & 1] + (c - 2) * 8192) : nullptr;
    else             src = (t >= 2) ? (g_h1[t & 1] + (c - 6) * 8192) : nullptr;
    if (src) {
        for (int i = tid; i < 2048; i += NTHR)
            cp16(dst + i * 4, src + i * 4);
    } else {
        float4 z = make_float4(0.f, 0.f, 0.f, 0.f);
        for (int i = tid; i < 2048; i += NTHR)
            reinterpret_cast<float4*>(dst)[i] = z;
    }
    CP_COMMIT;
}

__global__ void __launch_bounds__(NTHR, 1)
lstm2_kernel(const float* __restrict__ x,
             const float* __restrict__ Wih0, const float* __restrict__ bih0,
             const float* __restrict__ Whh0, const float* __restrict__ bhh0,
             const float* __restrict__ Wih1, const float* __restrict__ bih1,
             const float* __restrict__ Whh1, const float* __restrict__ bhh1,
             float* __restrict__ out)
{
    extern __shared__ char smraw[];
    ull*   w0d    = reinterpret_cast<ull*>(smraw);            // [768][16] lane-dup
    ull*   w1d    = w0d + 768 * 16;                           // [768][8]
    float* bcol   = reinterpret_cast<float*>(w1d + 768 * 8);  // [24] (+pad to 32)
    float* gates0 = bcol + 32;                                // [16][64]
    float* gates1 = gates0 + 16 * BATCH;                      // [8][64]
    float* vbase  = gates1 + 8 * BATCH;                       // 2 x 32KB chunk buffers
    ull*   red0   = reinterpret_cast<ull*>(vbase);            // [16][8][32] (aliased)
    ull*   red1   = red0 + 16 * 8 * 32;                       // [8][8][32]

    const int tid = threadIdx.x;
    const int cta = blockIdx.x;
    const int ks  = tid >> 5;            // warp id 0..23 = k residue (mod 24)
    const int pg  = (tid & 31) >> 2;     // pair group: pairs 4pg..4pg+3
    const int cg  = tid & 3;             // col group (gate index)

    // ---- one-time: transpose x (B,T,K) -> g_xT (T,K,B) ----
    {
        const size_t total = (size_t)BATCH * T_STEPS * 64;    // float4 groups
        for (size_t idx = (size_t)cta * NTHR + tid; idx < total; idx += (size_t)NCTA * NTHR) {
            int b  = (int)(idx & 63);
            size_t r = idx >> 6;
            int kg = (int)(r & 63);
            int t  = (int)(r >> 6);
            float4 v4 = *reinterpret_cast<const float4*>(
                x + ((size_t)b * T_STEPS + t) * 256 + kg * 4);
            float* dst = g_xT + ((size_t)t * 256 + kg * 4) * BATCH + b;
            dst[0 * BATCH] = v4.x;
            dst[1 * BATCH] = v4.y;
            dst[2 * BATCH] = v4.z;
            dst[3 * BATCH] = v4.w;
        }
    }

    // ---- one-time: stage weights (lane-duplicated for f32x2) ----
    // L0 smem col cc = g*4 + u -> global j = g*512 + cta*4 + u
    for (int idx = tid; idx < 768 * 16; idx += NTHR) {
        int k = idx >> 4, cc = idx & 15;
        int g = cc >> 2, u = cc & 3;
        int j = g * 512 + cta * 4 + u;
        float w = (k < 256) ? Wih0[(size_t)k * 2048 + j]
                            : Whh0[(size_t)(k - 256) * 2048 + j];
        w0d[idx] = dup32(w);
    }
    // L1 smem col cc1 = g*2 + u1 -> global j = g*256 + cta*2 + u1
    for (int idx = tid; idx < 768 * 8; idx += NTHR) {
        int k = idx >> 3, cc = idx & 7;
        int g = cc >> 1, u1 = cc & 1;
        int j = g * 256 + cta * 2 + u1;
        float w = (k < 512) ? Wih1[(size_t)k * 1024 + j]
                            : Whh1[(size_t)(k - 512) * 1024 + j];
        w1d[idx] = dup32(w);
    }
    if (tid < 16) {
        int g = tid >> 2, u = tid & 3;
        int j = g * 512 + cta * 4 + u;
        bcol[tid] = bih0[j] + bhh0[j];
    } else if (tid < 24) {
        int cc = tid - 16, g = cc >> 1, u1 = cc & 1;
        int j = g * 256 + cta * 2 + u1;
        bcol[tid] = bih1[j] + bhh1[j];
    }

    float cst = 0.0f;   // c0 for tid<256 (unit tid>>6, batch tid&63); c1 for [256,384)

    __syncthreads();
    grid_barrier();     // g_xT complete

    // ---- main recurrence: iteration t = layer0 step t + layer1 step t-1 ----
    for (int t = 0; t <= T_STEPS; t++) {
        const bool hasL0 = (t < T_STEPS);
        const bool hasL1 = (t >= 1);
        const int clo = hasL0 ? 0 : 2;
        const int chi = hasL1 ? 8 : 6;

        ull a0[16], a1[8];
#pragma unroll
        for (int j = 0; j < 16; j++) a0[j] = 0ull;
#pragma unroll
        for (int j = 0; j < 8; j++) a1[j] = 0ull;

        stage_chunk(vbase + (clo & 1) * 8192, clo, t, tid);

#pragma unroll 1
        for (int c = clo; c < chi; c++) {
            if (c + 1 < chi) {
                stage_chunk(vbase + ((c + 1) & 1) * 8192, c + 1, t, tid);
                CP_WAIT1;
            } else {
                CP_WAIT0;
            }
            __syncthreads();
            const float* vb = vbase + (c & 1) * 8192;

            // ---- L0 slice: k in chunk, k ≡ ks (mod 24) ----
            if (hasL0 && c < 6) {
                int rem = (128 * c) % 24;
                int off = ks - rem; if (off < 0) off += 24;
                const float* vp = vb + off * 64 + pg * 8;
                const ull*   wp = w0d + (size_t)(128 * c + off) * 16 + 4 * cg;
#pragma unroll 3
                for (int lr = off; lr < 128; lr += 24) {
                    ulonglong2 v01 = *reinterpret_cast<const ulonglong2*>(vp);
                    ulonglong2 v23 = *reinterpret_cast<const ulonglong2*>(vp + 4);
                    ulonglong2 wA  = *reinterpret_cast<const ulonglong2*>(wp);
                    ulonglong2 wB  = *reinterpret_cast<const ulonglong2*>(wp + 2);
                    vp += 24 * 64; wp += 24 * 16;
                    a0[0]  = ffma2(wA.x, v01.x, a0[0]);  a0[1]  = ffma2(wA.x, v01.y, a0[1]);
                    a0[2]  = ffma2(wA.x, v23.x, a0[2]);  a0[3]  = ffma2(wA.x, v23.y, a0[3]);
                    a0[4]  = ffma2(wA.y, v01.x, a0[4]);  a0[5]  = ffma2(wA.y, v01.y, a0[5]);
                    a0[6]  = ffma2(wA.y, v23.x, a0[6]);  a0[7]  = ffma2(wA.y, v23.y, a0[7]);
                    a0[8]  = ffma2(wB.x, v01.x, a0[8]);  a0[9]  = ffma2(wB.x, v01.y, a0[9]);
                    a0[10] = ffma2(wB.x, v23.x, a0[10]); a0[11] = ffma2(wB.x, v23.y, a0[11]);
                    a0[12] = ffma2(wB.y, v01.x, a0[12]); a0[13] = ffma2(wB.y, v01.y, a0[13]);
                    a0[14] = ffma2(wB.y, v23.x, a0[14]); a0[15] = ffma2(wB.y, v23.y, a0[15]);
                }
            }
            // ---- L1 slice: local k1 = gk-256 in chunk, k1 ≡ ks (mod 24) ----
            if (hasL1 && c >= 2) {
                int rem = (128 * (c - 2)) % 24;
                int off = ks - rem; if (off < 0) off += 24;
                const float* vp = vb + off * 64 + pg * 8;
                const ull*   wp = w1d + (size_t)(128 * (c - 2) + off) * 8 + 2 * cg;
#pragma unroll 3
                for (int lr = off; lr < 128; lr += 24) {
                    ulonglong2 v01 = *reinterpret_cast<const ulonglong2*>(vp);
                    ulonglong2 v23 = *reinterpret_cast<const ulonglong2*>(vp + 4);
                    ulonglong2 wA  = *reinterpret_cast<const ulonglong2*>(wp);
                    vp += 24 * 64; wp += 24 * 8;
                    a1[0] = ffma2(wA.x, v01.x, a1[0]);  a1[1] = ffma2(wA.x, v01.y, a1[1]);
                    a1[2] = ffma2(wA.x, v23.x, a1[2]);  a1[3] = ffma2(wA.x, v23.y, a1[3]);
                    a1[4] = ffma2(wA.y, v01.x, a1[4]);  a1[5] = ffma2(wA.y, v01.y, a1[5]);
                    a1[6] = ffma2(wA.y, v23.x, a1[6]);  a1[7] = ffma2(wA.y, v23.y, a1[7]);
                }
            }
            __syncthreads();     // chunk consumed -> buffer reusable
        }

        // ---- 3-wave ks reduction into 8 slots (red aliased over vbuf) ----
        const int slot = ks & 7;
        if (ks < 8) {
#pragma unroll
            for (int j = 0; j < 4; j++) {
                ull* d = red0 + ((4 * cg + j) * 8 + slot) * 32 + 4 * pg;
                *reinterpret_cast<ulonglong2*>(d)     = make_ulonglong2(a0[j * 4 + 0], a0[j * 4 + 1]);
                *reinterpret_cast<ulonglong2*>(d + 2) = make_ulonglong2(a0[j * 4 + 2], a0[j * 4 + 3]);
            }
#pragma unroll
            for (int j = 0; j < 2; j++) {
                ull* d = red1 + ((2 * cg + j) * 8 + slot) * 32 + 4 * pg;
                *reinterpret_cast<ulonglong2*>(d)     = make_ulonglong2(a1[j * 4 + 0], a1[j * 4 + 1]);
                *reinterpret_cast<ulonglong2*>(d + 2) = make_ulonglong2(a1[j * 4 + 2], a1[j * 4 + 3]);
            }
        }
        __syncthreads();
        if (ks >= 8 && ks < 16) {
#pragma unroll
            for (int j = 0; j < 4; j++) {
                ull* d = red0 + ((4 * cg + j) * 8 + slot) * 32 + 4 * pg;
                ulonglong2 r0 = *reinterpret_cast<ulonglong2*>(d);
                ulonglong2 r1 = *reinterpret_cast<ulonglong2*>(d + 2);
                r0.x = addf2(r0.x, a0[j * 4 + 0]); r0.y = addf2(r0.y, a0[j * 4 + 1]);
                r1.x = addf2(r1.x, a0[j * 4 + 2]); r1.y = addf2(r1.y, a0[j * 4 + 3]);
                *reinterpret_cast<ulonglong2*>(d) = r0;
                *reinterpret_cast<ulonglong2*>(d + 2) = r1;
            }
#pragma unroll
            for (int j = 0; j < 2; j++) {
                ull* d = red1 + ((2 * cg + j) * 8 + slot) * 32 + 4 * pg;
                ulonglong2 r0 = *reinterpret_cast<ulonglong2*>(d);
                ulonglong2 r1 = *reinterpret_cast<ulonglong2*>(d + 2);
                r0.x = addf2(r0.x, a1[j * 4 + 0]); r0.y = addf2(r0.y, a1[j * 4 + 1]);
                r1.x = addf2(r1.x, a1[j * 4 + 2]); r1.y = addf2(r1.y, a1[j * 4 + 3]);
                *reinterpret_cast<ulonglong2*>(d) = r0;
                *reinterpret_cast<ulonglong2*>(d + 2) = r1;
            }
        }
        __syncthreads();
        if (ks >= 16) {
#pragma unroll
            for (int j = 0; j < 4; j++) {
                ull* d = red0 + ((4 * cg + j) * 8 + slot) * 32 + 4 * pg;
                ulonglong2 r0 = *reinterpret_cast<ulonglong2*>(d);
                ulonglong2 r1 = *reinterpret_cast<ulonglong2*>(d + 2);
                r0.x = addf2(r0.x, a0[j * 4 + 0]); r0.y = addf2(r0.y, a0[j * 4 + 1]);
                r1.x = addf2(r1.x, a0[j * 4 + 2]); r1.y = addf2(r1.y, a0[j * 4 + 3]);
                *reinterpret_cast<ulonglong2*>(d) = r0;
                *reinterpret_cast<ulonglong2*>(d + 2) = r1;
            }
#pragma unroll
            for (int j = 0; j < 2; j++) {
                ull* d = red1 + ((2 * cg + j) * 8 + slot) * 32 + 4 * pg;
                ulonglong2 r0 = *reinterpret_cast<ulonglong2*>(d);
                ulonglong2 r1 = *reinterpret_cast<ulonglong2*>(d + 2);
                r0.x = addf2(r0.x, a1[j * 4 + 0]); r0.y = addf2(r0.y, a1[j * 4 + 1]);
                r1.x = addf2(r1.x, a1[j * 4 + 2]); r1.y = addf2(r1.y, a1[j * 4 + 3]);
                *reinterpret_cast<ulonglong2*>(d) = r0;
                *reinterpret_cast<ulonglong2*>(d + 2) = r1;
            }
        }
        __syncthreads();

        // ---- final: sum 8 slots + bias -> gates (768 threads, 1 each) ----
        if (tid < 512) {
            int cc = tid >> 5, pr = tid & 31;
            const ull* r = red0 + (cc * 8) * 32 + pr;
            ull s = dup32(bcol[cc]);
#pragma unroll
            for (int w = 0; w < 8; w++) s = addf2(s, r[w * 32]);
            *reinterpret_cast<ull*>(&gates0[cc * 64 + 2 * pr]) = s;
        } else {
            int i = tid - 512, cc = i >> 5, pr = i & 31;
            const ull* r = red1 + (cc * 8) * 32 + pr;
            ull s = dup32(bcol[16 + cc]);
#pragma unroll
            for (int w = 0; w < 8; w++) s = addf2(s, r[w * 32]);
            *reinterpret_cast<ull*>(&gates1[cc * 64 + 2 * pr]) = s;
        }
        __syncthreads();

        // ---- activations (disjoint warps) ----
        if (hasL0 && tid < 256) {
            int u = tid >> 6, b = tid & 63;
            float gi = gates0[(0 * 4 + u) * 64 + b];
            float gf = gates0[(1 * 4 + u) * 64 + b];
            float gg = gates0[(2 * 4 + u) * 64 + b];
            float go = gates0[(3 * 4 + u) * 64 + b];
            cst = sigmf(gf) * cst + sigmf(gi) * tanhf(gg);
            g_h0[t & 1][(cta * 4 + u) * 64 + b] = sigmf(go) * tanhf(cst);
        }
        if (hasL1 && tid >= 256 && tid < 384) {
            int u1 = (tid >> 6) & 1, b = tid & 63;
            float gi = gates1[(0 * 2 + u1) * 64 + b];
            float gf = gates1[(1 * 2 + u1) * 64 + b];
            float gg = gates1[(2 * 2 + u1) * 64 + b];
            float go = gates1[(3 * 2 + u1) * 64 + b];
            cst = sigmf(gf) * cst + sigmf(gi) * tanhf(gg);
            float h = sigmf(go) * tanhf(cst);
            int s = t - 1;
            g_h1[s & 1][(cta * 2 + u1) * 64 + b] = h;
            out[((size_t)b * T_STEPS + s) * 256 + cta * 2 + u1] = h;
        }

        if (t < T_STEPS) grid_barrier();
    }
}

// smem: w0d 98304 + w1d 49152 + bcol 128 + gates 6144 + vbuf 65536 = 219264
#define SMEM_BYTES (98304 + 49152 + 128 + 4096 + 2048 + 65536)

extern "C" void kernel_launch(void* const* d_in, const int* in_sizes, int n_in,
                              void* d_out, int out_size) {
    (void)in_sizes; (void)n_in; (void)out_size;
    cudaFuncSetAttribute(lstm2_kernel,
                         cudaFuncAttributeMaxDynamicSharedMemorySize, SMEM_BYTES);
    lstm2_kernel<<<NCTA, NTHR, SMEM_BYTES>>>(
        (const float*)d_in[0],
        (const float*)d_in[1], (const float*)d_in[2],
        (const float*)d_in[3], (const float*)d_in[4],
        (const float*)d_in[5], (const float*)d_in[6],
        (const float*)d_in[7], (const float*)d_in[8],
        (float*)d_out);
}

// round 9
// speedup vs baseline: 1.2247x; 1.2247x over previous
#include <cuda_runtime.h>

typedef unsigned long long ull;

#define T_STEPS 1024
#define BATCH   64
#define NCTA    128
#define NTHR    768

// Per-step input vector v (K=1024 rows x 64 batch) read DIRECTLY from global (L2):
//   rows [0,256)    = x_t        (layer0 only)
//   rows [256,768)  = h0_{t-1}   (both layers)
//   rows [768,1024) = h1_{t-2}   (layer1 only)
// L0 GEMM k in [0,768); L1 GEMM local k1 = k-256 in [0,768).
// Contiguous k-split: warp ks (0..23) owns k in [32ks, 32ks+32) for both layers
// -> each v row is read by exactly ONE warp -> no smem staging, no mid-GEMM syncs.
// Lane: pg = (lane>>1) in [0,16) -> pairs 2pg,2pg+1 (batches 4pg..4pg+3)
//       cl = lane&1 -> L0 cols cl*8..cl*8+7, L1 cols cl*4..cl*4+3
// Accums: a0[16] (8 cols x 2 pair-ulls) + a1[8] = 24 ull.
// 24 ks-partials reduced in 3 waves into 8 slots in dedicated smem (no aliasing).

__device__ float g_xT[T_STEPS * 256 * BATCH];   // x transposed to [t][k][b]
__device__ float g_h0[2][512 * BATCH];
__device__ float g_h1[2][256 * BATCH];
__device__ unsigned g_count = 0;
__device__ volatile unsigned g_phase = 0;

__device__ __forceinline__ ull ffma2(ull a, ull b, ull c) {
    ull d;
    asm("fma.rn.f32x2 %0, %1, %2, %3;" : "=l"(d) : "l"(a), "l"(b), "l"(c));
    return d;
}
__device__ __forceinline__ ull addf2(ull a, ull b) {
    ull d;
    asm("add.rn.f32x2 %0, %1, %2;" : "=l"(d) : "l"(a), "l"(b));
    return d;
}
__device__ __forceinline__ ull dup32(float w) {
    unsigned u = __float_as_uint(w);
    return ((ull)u << 32) | (ull)u;
}
__device__ __forceinline__ float sigmf(float x) {
    return 1.0f / (1.0f + __expf(-x));
}

// Sense-reversing grid barrier. Safe: ~203KB smem -> 1 CTA/SM, 128 CTAs <= 148 SMs,
// all co-resident in wave 1. Count self-resets -> consistent across graph replays.
__device__ __forceinline__ void grid_barrier() {
    __syncthreads();
    if (threadIdx.x == 0) {
        __threadfence();
        unsigned ph = g_phase;
        if (atomicAdd(&g_count, 1u) == (unsigned)(gridDim.x - 1)) {
            atomicExch(&g_count, 0u);
            __threadfence();
            g_phase = ph + 1u;
        } else {
            while (g_phase == ph) { __nanosleep(32); }
            __threadfence();
        }
    }
    __syncthreads();
}

// 32-row GEMM slice, 8 cols x 2 pair-ulls, v from global with prefetch-2 ring.
__device__ __forceinline__ void gemm32_c8(const ulonglong2* __restrict__ vsrc,
                                          const ull* __restrict__ wp,
                                          ull* __restrict__ a, int pg) {
    ulonglong2 v0 = vsrc[pg];
    ulonglong2 v1 = vsrc[16 + pg];
    const ulonglong2* vnext = vsrc + 32 + pg;
#pragma unroll 2
    for (int r = 0; r < 32; r++) {
        ulonglong2 v = (r & 1) ? v1 : v0;
        if (r + 2 < 32) {
            if (r & 1) v1 = *vnext; else v0 = *vnext;
            vnext += 16;
        }
        ulonglong2 wA = *reinterpret_cast<const ulonglong2*>(wp + 0);
        ulonglong2 wB = *reinterpret_cast<const ulonglong2*>(wp + 2);
        a[0]  = ffma2(wA.x, v.x, a[0]);   a[1]  = ffma2(wA.x, v.y, a[1]);
        a[2]  = ffma2(wA.y, v.x, a[2]);   a[3]  = ffma2(wA.y, v.y, a[3]);
        a[4]  = ffma2(wB.x, v.x, a[4]);   a[5]  = ffma2(wB.x, v.y, a[5]);
        a[6]  = ffma2(wB.y, v.x, a[6]);   a[7]  = ffma2(wB.y, v.y, a[7]);
        ulonglong2 wC = *reinterpret_cast<const ulonglong2*>(wp + 4);
        ulonglong2 wD = *reinterpret_cast<const ulonglong2*>(wp + 6);
        wp += 16;
        a[8]  = ffma2(wC.x, v.x, a[8]);   a[9]  = ffma2(wC.x, v.y, a[9]);
        a[10] = ffma2(wC.y, v.x, a[10]);  a[11] = ffma2(wC.y, v.y, a[11]);
        a[12] = ffma2(wD.x, v.x, a[12]);  a[13] = ffma2(wD.x, v.y, a[13]);
        a[14] = ffma2(wD.y, v.x, a[14]);  a[15] = ffma2(wD.y, v.y, a[15]);
    }
}

// 32-row GEMM slice, 4 cols x 2 pair-ulls.
__device__ __forceinline__ void gemm32_c4(const ulonglong2* __restrict__ vsrc,
                                          const ull* __restrict__ wp,
                                          ull* __restrict__ a, int pg) {
    ulonglong2 v0 = vsrc[pg];
    ulonglong2 v1 = vsrc[16 + pg];
    const ulonglong2* vnext = vsrc + 32 + pg;
#pragma unroll 2
    for (int r = 0; r < 32; r++) {
        ulonglong2 v = (r & 1) ? v1 : v0;
        if (r + 2 < 32) {
            if (r & 1) v1 = *vnext; else v0 = *vnext;
            vnext += 16;
        }
        ulonglong2 wA = *reinterpret_cast<const ulonglong2*>(wp + 0);
        ulonglong2 wB = *reinterpret_cast<const ulonglong2*>(wp + 2);
        wp += 8;
        a[0] = ffma2(wA.x, v.x, a[0]);  a[1] = ffma2(wA.x, v.y, a[1]);
        a[2] = ffma2(wA.y, v.x, a[2]);  a[3] = ffma2(wA.y, v.y, a[3]);
        a[4] = ffma2(wB.x, v.x, a[4]);  a[5] = ffma2(wB.x, v.y, a[5]);
        a[6] = ffma2(wB.y, v.x, a[6]);  a[7] = ffma2(wB.y, v.y, a[7]);
    }
}

__global__ void __launch_bounds__(NTHR, 1)
lstm2_kernel(const float* __restrict__ x,
             const float* __restrict__ Wih0, const float* __restrict__ bih0,
             const float* __restrict__ Whh0, const float* __restrict__ bhh0,
             const float* __restrict__ Wih1, const float* __restrict__ bih1,
             const float* __restrict__ Whh1, const float* __restrict__ bhh1,
             float* __restrict__ out)
{
    extern __shared__ char smraw[];
    ull*   w0d    = reinterpret_cast<ull*>(smraw);            // [768][16] lane-dup
    ull*   w1d    = w0d + 768 * 16;                           // [768][8]
    float* bcol   = reinterpret_cast<float*>(w1d + 768 * 8);  // [24] pad 32
    float* gates0 = bcol + 32;                                // [16][64]
    float* gates1 = gates0 + 16 * BATCH;                      // [8][64]
    ull*   red0   = reinterpret_cast<ull*>(gates1 + 8 * BATCH); // [16][8][32]
    ull*   red1   = red0 + 16 * 8 * 32;                       // [8][8][32]

    const int tid = threadIdx.x;
    const int cta = blockIdx.x;
    const int ks  = tid >> 5;            // warp id 0..23: k in [32ks, 32ks+32)
    const int pg  = (tid & 31) >> 1;     // pair group 0..15: pairs 2pg,2pg+1
    const int cl  = tid & 1;             // col half

    // ---- one-time: transpose x (B,T,K) -> g_xT (T,K,B) ----
    {
        const size_t total = (size_t)BATCH * T_STEPS * 64;    // float4 groups
        for (size_t idx = (size_t)cta * NTHR + tid; idx < total; idx += (size_t)NCTA * NTHR) {
            int b  = (int)(idx & 63);
            size_t r = idx >> 6;
            int kg = (int)(r & 63);
            int t  = (int)(r >> 6);
            float4 v4 = *reinterpret_cast<const float4*>(
                x + ((size_t)b * T_STEPS + t) * 256 + kg * 4);
            float* dst = g_xT + ((size_t)t * 256 + kg * 4) * BATCH + b;
            dst[0 * BATCH] = v4.x;
            dst[1 * BATCH] = v4.y;
            dst[2 * BATCH] = v4.z;
            dst[3 * BATCH] = v4.w;
        }
    }

    // ---- one-time: stage weights into smem (lane-duplicated for f32x2) ----
    // L0 smem col cc = g*4 + u -> global j = g*512 + cta*4 + u
    for (int idx = tid; idx < 768 * 16; idx += NTHR) {
        int k = idx >> 4, cc = idx & 15;
        int g = cc >> 2, u = cc & 3;
        int j = g * 512 + cta * 4 + u;
        float w = (k < 256) ? Wih0[(size_t)k * 2048 + j]
                            : Whh0[(size_t)(k - 256) * 2048 + j];
        w0d[idx] = dup32(w);
    }
    // L1 smem col cc = g*2 + u1 -> global j = g*256 + cta*2 + u1
    for (int idx = tid; idx < 768 * 8; idx += NTHR) {
        int k = idx >> 3, cc = idx & 7;
        int g = cc >> 1, u1 = cc & 1;
        int j = g * 256 + cta * 2 + u1;
        float w = (k < 512) ? Wih1[(size_t)k * 1024 + j]
                            : Whh1[(size_t)(k - 512) * 1024 + j];
        w1d[idx] = dup32(w);
    }
    if (tid < 16) {
        int g = tid >> 2, u = tid & 3;
        int j = g * 512 + cta * 4 + u;
        bcol[tid] = bih0[j] + bhh0[j];
    } else if (tid < 24) {
        int cc = tid - 16, g = cc >> 1, u1 = cc & 1;
        int j = g * 256 + cta * 2 + u1;
        bcol[tid] = bih1[j] + bhh1[j];
    }

    float cst = 0.0f;   // c0 for tid<256 (unit tid>>6, batch tid&63); c1 for [256,384)

    __syncthreads();
    grid_barrier();     // g_xT complete

    // ---- main recurrence: iteration t = layer0 step t + layer1 step t-1 ----
    for (int t = 0; t <= T_STEPS; t++) {
        const bool hasL0 = (t < T_STEPS);
        const bool hasL1 = (t >= 1);

        ull a0[16], a1[8];
#pragma unroll
        for (int j = 0; j < 16; j++) a0[j] = 0ull;
#pragma unroll
        for (int j = 0; j < 8; j++) a1[j] = 0ull;

        // ---- L0 slice: k in [32ks, 32ks+32); sources: ks<8 -> x_t, else h0_{t-1} ----
        if (hasL0 && (ks < 8 || t >= 1)) {
            const float* src = (ks < 8)
                ? (g_xT + (size_t)t * 16384 + ks * 2048)
                : (g_h0[(t - 1) & 1] + (ks - 8) * 2048);
            gemm32_c8(reinterpret_cast<const ulonglong2*>(src),
                      w0d + (size_t)(32 * ks) * 16 + cl * 8, a0, pg);
        }
        // ---- L1 slice: local k1 in [32ks, 32ks+32); ks<16 -> h0_{t-1}, else h1_{t-2} ----
        if (hasL1 && (ks < 16 || t >= 2)) {
            const float* src = (ks < 16)
                ? (g_h0[(t - 1) & 1] + ks * 2048)
                : (g_h1[t & 1] + (ks - 16) * 2048);
            gemm32_c4(reinterpret_cast<const ulonglong2*>(src),
                      w1d + (size_t)(32 * ks) * 8 + cl * 4, a1, pg);
        }

        // ---- 3-wave ks reduction into 8 slots ----
        const int slot = ks & 7;
        if (ks < 8) {
#pragma unroll
            for (int j = 0; j < 8; j++)
                *reinterpret_cast<ulonglong2*>(
                    red0 + ((cl * 8 + j) * 8 + slot) * 32 + 2 * pg) =
                    make_ulonglong2(a0[2 * j], a0[2 * j + 1]);
#pragma unroll
            for (int j = 0; j < 4; j++)
                *reinterpret_cast<ulonglong2*>(
                    red1 + ((cl * 4 + j) * 8 + slot) * 32 + 2 * pg) =
                    make_ulonglong2(a1[2 * j], a1[2 * j + 1]);
        }
        __syncthreads();
        if (ks >= 8 && ks < 16) {
#pragma unroll
            for (int j = 0; j < 8; j++) {
                ull* d = red0 + ((cl * 8 + j) * 8 + slot) * 32 + 2 * pg;
                ulonglong2 r = *reinterpret_cast<ulonglong2*>(d);
                r.x = addf2(r.x, a0[2 * j]); r.y = addf2(r.y, a0[2 * j + 1]);
                *reinterpret_cast<ulonglong2*>(d) = r;
            }
#pragma unroll
            for (int j = 0; j < 4; j++) {
                ull* d = red1 + ((cl * 4 + j) * 8 + slot) * 32 + 2 * pg;
                ulonglong2 r = *reinterpret_cast<ulonglong2*>(d);
                r.x = addf2(r.x, a1[2 * j]); r.y = addf2(r.y, a1[2 * j + 1]);
                *reinterpret_cast<ulonglong2*>(d) = r;
            }
        }
        __syncthreads();
        if (ks >= 16) {
#pragma unroll
            for (int j = 0; j < 8; j++) {
                ull* d = red0 + ((cl * 8 + j) * 8 + slot) * 32 + 2 * pg;
                ulonglong2 r = *reinterpret_cast<ulonglong2*>(d);
                r.x = addf2(r.x, a0[2 * j]); r.y = addf2(r.y, a0[2 * j + 1]);
                *reinterpret_cast<ulonglong2*>(d) = r;
            }
#pragma unroll
            for (int j = 0; j < 4; j++) {
                ull* d = red1 + ((cl * 4 + j) * 8 + slot) * 32 + 2 * pg;
                ulonglong2 r = *reinterpret_cast<ulonglong2*>(d);
                r.x = addf2(r.x, a1[2 * j]); r.y = addf2(r.y, a1[2 * j + 1]);
                *reinterpret_cast<ulonglong2*>(d) = r;
            }
        }
        __syncthreads();

        // ---- final: sum 8 slots + bias -> gates (one ull per thread) ----
        if (tid < 512) {
            int cc = tid >> 5, pr = tid & 31;
            const ull* r = red0 + (cc * 8) * 32 + pr;
            ull s = dup32(bcol[cc]);
#pragma unroll
            for (int w = 0; w < 8; w++) s = addf2(s, r[w * 32]);
            *reinterpret_cast<ull*>(&gates0[cc * 64 + 2 * pr]) = s;
        } else {
            int i = tid - 512, cc = i >> 5, pr = i & 31;
            const ull* r = red1 + (cc * 8) * 32 + pr;
            ull s = dup32(bcol[16 + cc]);
#pragma unroll
            for (int w = 0; w < 8; w++) s = addf2(s, r[w * 32]);
            *reinterpret_cast<ull*>(&gates1[cc * 64 + 2 * pr]) = s;
        }
        __syncthreads();

        // ---- activations (disjoint warps) ----
        if (hasL0 && tid < 256) {
            int u = tid >> 6, b = tid & 63;
            float gi = gates0[(0 * 4 + u) * 64 + b];
            float gf = gates0[(1 * 4 + u) * 64 + b];
            float gg = gates0[(2 * 4 + u) * 64 + b];
            float go = gates0[(3 * 4 + u) * 64 + b];
            cst = sigmf(gf) * cst + sigmf(gi) * tanhf(gg);
            g_h0[t & 1][(cta * 4 + u) * 64 + b] = sigmf(go) * tanhf(cst);
        }
        if (hasL1 && tid >= 256 && tid < 384) {
            int u1 = (tid >> 6) & 1, b = tid & 63;
            float gi = gates1[(0 * 2 + u1) * 64 + b];
            float gf = gates1[(1 * 2 + u1) * 64 + b];
            float gg = gates1[(2 * 2 + u1) * 64 + b];
            float go = gates1[(3 * 2 + u1) * 64 + b];
            cst = sigmf(gf) * cst + sigmf(gi) * tanhf(gg);
            float h = sigmf(go) * tanhf(cst);
            int s = t - 1;
            g_h1[s & 1][(cta * 2 + u1) * 64 + b] = h;
            out[((size_t)b * T_STEPS + s) * 256 + cta * 2 + u1] = h;
        }

        if (t < T_STEPS) grid_barrier();
    }
}

// smem: w0d 98304 + w1d 49152 + bcol 128 + gates 6144 + red0 32768 + red1 16384
#define SMEM_BYTES (98304 + 49152 + 128 + 4096 + 2048 + 32768 + 16384)

extern "C" void kernel_launch(void* const* d_in, const int* in_sizes, int n_in,
                              void* d_out, int out_size) {
    (void)in_sizes; (void)n_in; (void)out_size;
    cudaFuncSetAttribute(lstm2_kernel,
                         cudaFuncAttributeMaxDynamicSharedMemorySize, SMEM_BYTES);
    lstm2_kernel<<<NCTA, NTHR, SMEM_BYTES>>>(
        (const float*)d_in[0],
        (const float*)d_in[1], (const float*)d_in[2],
        (const float*)d_in[3], (const float*)d_in[4],
        (const float*)d_in[5], (const float*)d_in[6],
        (const float*)d_in[7], (const float*)d_in[8],
        (float*)d_out);
}